// round 7
// baseline (speedup 1.0000x reference)
#include <cuda_runtime.h>
#include <cuda_bf16.h>
#include <cooperative_groups.h>
#include <cstdint>

namespace cg = cooperative_groups;

#define NUM_C 1024
#define EMB   512
#define HID   512
#define BATCH 64
#define SEQ   512
#define M_ROWS (BATCH * SEQ)   // 32768
#define NROWS 2048             // distinct embedding rows

// ---------------------------------------------------------------------------
// Device scratch
// ---------------------------------------------------------------------------
__device__ float g_table[(size_t)NROWS * HID];    // 4 MB: emb@Wx^T + bx + bh
__device__ float g_hs   [(size_t)M_ROWS * HID];   // 64 MB: scan outputs

// ---------------------------------------------------------------------------
// f32x2 helpers
// ---------------------------------------------------------------------------
__device__ __forceinline__ void fma2(unsigned long long& acc,
                                     unsigned long long a, unsigned long long b) {
    asm("fma.rn.f32x2 %0, %1, %2, %0;" : "+l"(acc) : "l"(a), "l"(b));
}
__device__ __forceinline__ unsigned long long pk2(float lo, float hi) {
    unsigned long long r;
    asm("mov.b64 %0, {%1, %2};" : "=l"(r) : "f"(lo), "f"(hi));
    return r;
}
__device__ __forceinline__ unsigned long long dup2(float x) {
    unsigned long long r;
    asm("mov.b64 %0, {%1, %1};" : "=l"(r) : "f"(x));
    return r;
}
__device__ __forceinline__ void upk2(unsigned long long v, float& lo, float& hi) {
    asm("mov.b64 {%0, %1}, %2;" : "=f"(lo), "=f"(hi) : "l"(v));
}
__device__ __forceinline__ void add2(unsigned long long& acc, unsigned long long a) {
    asm("add.rn.f32x2 %0, %1, %2;" : "=l"(acc) : "l"(acc), "l"(a));
}

// ---------------------------------------------------------------------------
// proj table GEMM: table[m][n] = sum_e emb[m][e]*Wx_w[n][e] + Wx_b[n] + Wh_b[n]
// ---------------------------------------------------------------------------
__global__ __launch_bounds__(256, 2)
void proj_kernel(const float* __restrict__ emb,
                 const float* __restrict__ Wx_w,
                 const float* __restrict__ Wx_b,
                 const float* __restrict__ Wh_b) {
    __shared__ float As[8][128];
    __shared__ float Bs[8][128];

    const int tid  = threadIdx.x;
    const int row0 = blockIdx.y * 128;
    const int col0 = blockIdx.x * 128;

    const int lr = tid >> 1;
    const int lc = (tid & 1) * 4;
    const int tx = tid & 15;
    const int ty = tid >> 4;

    const float* aptr = emb  + (size_t)(row0 + lr) * EMB;
    const float* bptr = Wx_w + (size_t)(col0 + lr) * EMB;

    unsigned long long accp[8][4];
#pragma unroll
    for (int i = 0; i < 8; i++)
#pragma unroll
        for (int j = 0; j < 4; j++) accp[i][j] = 0ull;

    float4 pa = *(const float4*)(aptr + lc);
    float4 pb = *(const float4*)(bptr + lc);

    for (int k0 = 0; k0 < EMB; k0 += 8) {
        __syncthreads();
        As[lc + 0][lr] = pa.x; As[lc + 1][lr] = pa.y;
        As[lc + 2][lr] = pa.z; As[lc + 3][lr] = pa.w;
        Bs[lc + 0][lr] = pb.x; Bs[lc + 1][lr] = pb.y;
        Bs[lc + 2][lr] = pb.z; Bs[lc + 3][lr] = pb.w;
        __syncthreads();

        if (k0 + 8 < EMB) {
            pa = *(const float4*)(aptr + k0 + 8 + lc);
            pb = *(const float4*)(bptr + k0 + 8 + lc);
        }

#pragma unroll
        for (int k = 0; k < 8; k++) {
            float4 a0 = *(const float4*)&As[k][ty * 8];
            float4 a1 = *(const float4*)&As[k][ty * 8 + 4];
            float4 b0 = *(const float4*)&Bs[k][tx * 8];
            float4 b1 = *(const float4*)&Bs[k][tx * 8 + 4];
            unsigned long long bp0 = pk2(b0.x, b0.y), bp1 = pk2(b0.z, b0.w);
            unsigned long long bp2 = pk2(b1.x, b1.y), bp3 = pk2(b1.z, b1.w);
            float av[8] = {a0.x, a0.y, a0.z, a0.w, a1.x, a1.y, a1.z, a1.w};
#pragma unroll
            for (int i = 0; i < 8; i++) {
                unsigned long long ad = dup2(av[i]);
                fma2(accp[i][0], ad, bp0);
                fma2(accp[i][1], ad, bp1);
                fma2(accp[i][2], ad, bp2);
                fma2(accp[i][3], ad, bp3);
            }
        }
    }

#pragma unroll
    for (int i = 0; i < 8; i++) {
        int m = row0 + ty * 8 + i;
        float* op = g_table + (size_t)m * HID + col0 + tx * 8;
#pragma unroll
        for (int jp = 0; jp < 4; jp++) {
            float v0, v1;
            upk2(accp[i][jp], v0, v1);
            int n = col0 + tx * 8 + jp * 2;
            op[jp * 2]     = v0 + Wx_b[n]     + Wh_b[n];
            op[jp * 2 + 1] = v1 + Wx_b[n + 1] + Wh_b[n + 1];
        }
    }
}

// ---------------------------------------------------------------------------
// Cluster scan, 256 threads (255-reg budget -> weights truly in registers).
// 16 clusters x 8 CTAs; CTA = 64 j x 4 b.
// Phase A thread: jpg = tid&31 (j-pair), ks = tid>>5 (64-k slice).
// Wh in regs as (wj0,wj1) u64 pairs: w2[64] = 128 regs.
// h in smem duplicated: [k][b0,b0,b1,b1,b2,b2,b3,b3] -> 2 broadcast LDS.128/k.
// ---------------------------------------------------------------------------
// smem: sh2 2*512*8 = 8192 f | srp 8*32*4 u64 = 2048 f | sidx 2048 ints
#define SCAN_SMEM_FLOATS (8192 + 2048 + 2048)
#define SCAN_SMEM_BYTES  (SCAN_SMEM_FLOATS * 4)   // 49,152 B

__global__ __launch_bounds__(256, 1) __cluster_dims__(8, 1, 1)
void scan_kernel(const int* __restrict__ q, const int* __restrict__ r,
                 const float* __restrict__ Wh_w,
                 const float* __restrict__ tau) {
    extern __shared__ float smem[];
    float*              sh2   = smem;                                  // [2][512][8]
    unsigned long long* srp   = (unsigned long long*)(smem + 8192);    // [8ks][32jp][4b]
    int*                sidxm = (int*)(smem + 8192 + 2048);            // [4b][512s]

    cg::cluster_group cluster = cg::this_cluster();
    const int rank = (int)cluster.block_rank();
    const int cid  = blockIdx.x >> 3;
    const int tid  = threadIdx.x;
    const int j0   = rank * 64;
    const int b0   = cid * 4;

    // ---- stage idx table ----
    for (int i = tid; i < 4 * SEQ; i += 256) {
        int b = i >> 9, s = i & 511;
        int m = (b0 + b) * SEQ + s;
        sidxm[i] = q[m] + NUM_C * r[m];
    }
    // ---- zero h buffer 0 ----
    for (int i = tid; i < 4096; i += 256) sh2[i] = 0.0f;

    // ---- phase A mapping + register Wh ----
    const int jpg = tid & 31;           // j-pair 0..31 -> j = 2jpg, 2jpg+1
    const int ks  = tid >> 5;           // 0..7, 64 k each

    unsigned long long w2[64];          // 128 regs: (w_{2jpg,k}, w_{2jpg+1,k})
    {
        const float* r0 = Wh_w + (size_t)(j0 + 2 * jpg)     * HID + ks * 64;
        const float* r1 = Wh_w + (size_t)(j0 + 2 * jpg + 1) * HID + ks * 64;
#pragma unroll
        for (int t = 0; t < 16; t++) {
            float4 f0 = *(const float4*)(r0 + t * 4);
            float4 f1 = *(const float4*)(r1 + t * 4);
            w2[t * 4 + 0] = pk2(f0.x, f1.x);
            w2[t * 4 + 1] = pk2(f0.y, f1.y);
            w2[t * 4 + 2] = pk2(f0.z, f1.z);
            w2[t * 4 + 3] = pk2(f0.w, f1.w);
        }
    }

    // ---- phase B mapping (tid<128) ----
    const int jp_b = tid & 31;
    const int b_b  = (tid >> 5) & 3;
    float it0 = 1.0f, it1 = 1.0f;
    if (tid < 128) {
        it0 = 1.0f / tau[j0 + 2 * jp_b];
        it1 = 1.0f / tau[j0 + 2 * jp_b + 1];
    }

    __syncthreads();
    cluster.sync();

    for (int s = 0; s < SEQ; s++) {
        const float* shc = sh2 + (s & 1) * 4096;
        float*       shn = sh2 + ((s + 1) & 1) * 4096;

        // phase-B prefetch (overlapped with phase A)
        float xp0 = 0.f, xp1 = 0.f, hold0 = 0.f, hold1 = 0.f;
        if (tid < 128) {
            int row = sidxm[b_b * SEQ + s];
            float2 xp2 = *(const float2*)&g_table[(size_t)row * HID + j0 + 2 * jp_b];
            xp0 = xp2.x; xp1 = xp2.y;
            hold0 = shc[(j0 + 2 * jp_b)     * 8 + b_b * 2];   // FIX: + j0
            hold1 = shc[(j0 + 2 * jp_b + 1) * 8 + b_b * 2];   // FIX: + j0
        }

        // ---- phase A: 64 k, 2 broadcast LDS.128 + 4 FFMA2 each ----
        unsigned long long acc0 = 0ull, acc1 = 0ull, acc2 = 0ull, acc3 = 0ull;
        const float* hp = shc + ks * 64 * 8;
#pragma unroll
        for (int kk = 0; kk < 64; kk++) {
            ulonglong2 u = *(const ulonglong2*)(hp + kk * 8);       // (b0b0),(b1b1)
            ulonglong2 v = *(const ulonglong2*)(hp + kk * 8 + 4);   // (b2b2),(b3b3)
            fma2(acc0, w2[kk], u.x);
            fma2(acc1, w2[kk], u.y);
            fma2(acc2, w2[kk], v.x);
            fma2(acc3, w2[kk], v.y);
        }
        {
            unsigned long long* rp = srp + (ks * 32 + jpg) * 4;
            rp[0] = acc0; rp[1] = acc1; rp[2] = acc2; rp[3] = acc3;
        }
        __syncthreads();

        // ---- phase B (tid<128): reduce 8 k-slices, LTC update ----
        if (tid < 128) {
            unsigned long long s2 = srp[(0 * 32 + jp_b) * 4 + b_b];
#pragma unroll
            for (int k2 = 1; k2 < 8; k2++)
                add2(s2, srp[(k2 * 32 + jp_b) * 4 + b_b]);
            float f0, f1;
            upk2(s2, f0, f1);
            float th0 = tanhf(f0 + xp0);
            float th1 = tanhf(f1 + xp1);
            float hn0 = hold0 + (th0 - hold0) * it0;
            float hn1 = hold1 + (th1 - hold1) * it1;

            *(float2*)&g_hs[((size_t)(b0 + b_b) * SEQ + s) * HID + j0 + 2 * jp_b]
                = make_float2(hn0, hn1);
            *(float2*)&shn[(j0 + 2 * jp_b)     * 8 + b_b * 2] = make_float2(hn0, hn0); // FIX: + j0
            *(float2*)&shn[(j0 + 2 * jp_b + 1) * 8 + b_b * 2] = make_float2(hn1, hn1); // FIX: + j0
        }
        __syncthreads();

        // ---- phase C: broadcast own dup slice (2KB) to 7 peers ----
        if (s < SEQ - 1) {
            for (int idx = tid; idx < 896; idx += 256) {
                int rk_i = idx >> 7;              // 0..6
                int rem  = idx & 127;             // float4 index in 2KB slice
                int rk   = rk_i + (rk_i >= rank);
                float4* src = (float4*)(shn + j0 * 8) + rem;
                float4  val = *src;
                float4* dst = cluster.map_shared_rank(src, rk);
                *dst = val;
            }
            cluster.sync();
        }
    }
}

// ---------------------------------------------------------------------------
// Output GEMM + sigmoid (f32x2 inner)
// ---------------------------------------------------------------------------
__global__ __launch_bounds__(256, 2)
void out_kernel(const float* __restrict__ Wo_w,
                const float* __restrict__ Wo_b,
                float* __restrict__ out) {
    __shared__ float As[8][128];
    __shared__ float Bs[8][128];

    const int tid  = threadIdx.x;
    const int row0 = blockIdx.y * 128;
    const int col0 = blockIdx.x * 128;

    const int lr = tid >> 1;
    const int lc = (tid & 1) * 4;
    const int tx = tid & 15;
    const int ty = tid >> 4;

    const float* aptr = g_hs + (size_t)(row0 + lr) * HID;
    const float* bptr = Wo_w + (size_t)(col0 + lr) * HID;

    unsigned long long accp[8][4];
#pragma unroll
    for (int i = 0; i < 8; i++)
#pragma unroll
        for (int j = 0; j < 4; j++) accp[i][j] = 0ull;

    float4 pa = *(const float4*)(aptr + lc);
    float4 pb = *(const float4*)(bptr + lc);

    for (int k0 = 0; k0 < HID; k0 += 8) {
        __syncthreads();
        As[lc + 0][lr] = pa.x; As[lc + 1][lr] = pa.y;
        As[lc + 2][lr] = pa.z; As[lc + 3][lr] = pa.w;
        Bs[lc + 0][lr] = pb.x; Bs[lc + 1][lr] = pb.y;
        Bs[lc + 2][lr] = pb.z; Bs[lc + 3][lr] = pb.w;
        __syncthreads();

        if (k0 + 8 < HID) {
            pa = *(const float4*)(aptr + k0 + 8 + lc);
            pb = *(const float4*)(bptr + k0 + 8 + lc);
        }

#pragma unroll
        for (int k = 0; k < 8; k++) {
            float4 a0 = *(const float4*)&As[k][ty * 8];
            float4 a1 = *(const float4*)&As[k][ty * 8 + 4];
            float4 b0 = *(const float4*)&Bs[k][tx * 8];
            float4 b1 = *(const float4*)&Bs[k][tx * 8 + 4];
            unsigned long long bp0 = pk2(b0.x, b0.y), bp1 = pk2(b0.z, b0.w);
            unsigned long long bp2 = pk2(b1.x, b1.y), bp3 = pk2(b1.z, b1.w);
            float av[8] = {a0.x, a0.y, a0.z, a0.w, a1.x, a1.y, a1.z, a1.w};
#pragma unroll
            for (int i = 0; i < 8; i++) {
                unsigned long long ad = dup2(av[i]);
                fma2(accp[i][0], ad, bp0);
                fma2(accp[i][1], ad, bp1);
                fma2(accp[i][2], ad, bp2);
                fma2(accp[i][3], ad, bp3);
            }
        }
    }

#pragma unroll
    for (int i = 0; i < 8; i++) {
        int m = row0 + ty * 8 + i;
        float* op = out + (size_t)m * NUM_C + col0 + tx * 8;
#pragma unroll
        for (int jp = 0; jp < 4; jp++) {
            float v0, v1;
            upk2(accp[i][jp], v0, v1);
            int n = col0 + tx * 8 + jp * 2;
            float l0 = v0 + Wo_b[n];
            float l1 = v1 + Wo_b[n + 1];
            op[jp * 2]     = 1.0f / (1.0f + expf(-l0));
            op[jp * 2 + 1] = 1.0f / (1.0f + expf(-l1));
        }
    }
}

// ---------------------------------------------------------------------------
extern "C" void kernel_launch(void* const* d_in, const int* in_sizes, int n_in,
                              void* d_out, int out_size) {
    const int*   q    = (const int*)  d_in[0];
    const int*   r    = (const int*)  d_in[1];
    const float* emb  = (const float*)d_in[2];
    const float* Wh_w = (const float*)d_in[3];
    const float* Wh_b = (const float*)d_in[4];
    const float* Wx_w = (const float*)d_in[5];
    const float* Wx_b = (const float*)d_in[6];
    const float* tau  = (const float*)d_in[7];
    const float* Wo_w = (const float*)d_in[8];
    const float* Wo_b = (const float*)d_in[9];
    float*       out  = (float*)d_out;

    cudaFuncSetAttribute(scan_kernel,
                         cudaFuncAttributeMaxDynamicSharedMemorySize,
                         SCAN_SMEM_BYTES);

    // 1) projection table: 2048 x 512 (biases folded)
    {
        dim3 grid(HID / 128, NROWS / 128);
        proj_kernel<<<grid, 256>>>(emb, Wx_w, Wx_b, Wh_b);
    }
    // 2) cluster scan: 128 CTAs = 16 clusters x 8 ranks, 256 threads
    scan_kernel<<<128, 256, SCAN_SMEM_BYTES>>>(q, r, Wh_w, tau);
    // 3) output GEMM + sigmoid
    {
        dim3 grid(NUM_C / 128, M_ROWS / 128);
        out_kernel<<<grid, 256>>>(Wo_w, Wo_b, out);
    }
}

// round 8
// speedup vs baseline: 1.1416x; 1.1416x over previous
#include <cuda_runtime.h>
#include <cuda_bf16.h>
#include <cooperative_groups.h>
#include <cstdint>

namespace cg = cooperative_groups;

#define NUM_C 1024
#define EMB   512
#define HID   512
#define BATCH 64
#define SEQ   512
#define M_ROWS (BATCH * SEQ)   // 32768
#define NROWS 2048             // distinct embedding rows

// ---------------------------------------------------------------------------
// Device scratch
// ---------------------------------------------------------------------------
__device__ float g_table[(size_t)NROWS * HID];    // 4 MB: emb@Wx^T + bx + bh
__device__ float g_hs   [(size_t)M_ROWS * HID];   // 64 MB: scan outputs

// ---------------------------------------------------------------------------
// f32x2 helpers
// ---------------------------------------------------------------------------
__device__ __forceinline__ void fma2(unsigned long long& acc,
                                     unsigned long long a, unsigned long long b) {
    asm("fma.rn.f32x2 %0, %1, %2, %0;" : "+l"(acc) : "l"(a), "l"(b));
}
__device__ __forceinline__ unsigned long long pk2(float lo, float hi) {
    unsigned long long r;
    asm("mov.b64 %0, {%1, %2};" : "=l"(r) : "f"(lo), "f"(hi));
    return r;
}
__device__ __forceinline__ unsigned long long dup2(float x) {
    unsigned long long r;
    asm("mov.b64 %0, {%1, %1};" : "=l"(r) : "f"(x));
    return r;
}
__device__ __forceinline__ void upk2(unsigned long long v, float& lo, float& hi) {
    asm("mov.b64 {%0, %1}, %2;" : "=f"(lo), "=f"(hi) : "l"(v));
}
__device__ __forceinline__ void add2(unsigned long long& acc, unsigned long long a) {
    asm("add.rn.f32x2 %0, %1, %2;" : "=l"(acc) : "l"(acc), "l"(a));
}
// split a (w0,w1) pair into dup'd (w0,w0) and (w1,w1)
__device__ __forceinline__ void dupsplit(unsigned long long w,
                                         unsigned long long& a, unsigned long long& b) {
    asm("{\n\t.reg .b32 lo,hi;\n\t"
        "mov.b64 {lo,hi}, %2;\n\t"
        "mov.b64 %0, {lo,lo};\n\t"
        "mov.b64 %1, {hi,hi};\n\t}"
        : "=l"(a), "=l"(b) : "l"(w));
}

#define CLUSTER_ARRIVE() asm volatile("barrier.cluster.arrive.aligned;" ::: "memory")
#define CLUSTER_WAIT()   asm volatile("barrier.cluster.wait.aligned;"   ::: "memory")

// ---------------------------------------------------------------------------
// proj table GEMM: table[m][n] = sum_e emb[m][e]*Wx_w[n][e] + Wx_b[n] + Wh_b[n]
// ---------------------------------------------------------------------------
__global__ __launch_bounds__(256, 2)
void proj_kernel(const float* __restrict__ emb,
                 const float* __restrict__ Wx_w,
                 const float* __restrict__ Wx_b,
                 const float* __restrict__ Wh_b) {
    __shared__ float As[8][128];
    __shared__ float Bs[8][128];

    const int tid  = threadIdx.x;
    const int row0 = blockIdx.y * 128;
    const int col0 = blockIdx.x * 128;

    const int lr = tid >> 1;
    const int lc = (tid & 1) * 4;
    const int tx = tid & 15;
    const int ty = tid >> 4;

    const float* aptr = emb  + (size_t)(row0 + lr) * EMB;
    const float* bptr = Wx_w + (size_t)(col0 + lr) * EMB;

    unsigned long long accp[8][4];
#pragma unroll
    for (int i = 0; i < 8; i++)
#pragma unroll
        for (int j = 0; j < 4; j++) accp[i][j] = 0ull;

    float4 pa = *(const float4*)(aptr + lc);
    float4 pb = *(const float4*)(bptr + lc);

    for (int k0 = 0; k0 < EMB; k0 += 8) {
        __syncthreads();
        As[lc + 0][lr] = pa.x; As[lc + 1][lr] = pa.y;
        As[lc + 2][lr] = pa.z; As[lc + 3][lr] = pa.w;
        Bs[lc + 0][lr] = pb.x; Bs[lc + 1][lr] = pb.y;
        Bs[lc + 2][lr] = pb.z; Bs[lc + 3][lr] = pb.w;
        __syncthreads();

        if (k0 + 8 < EMB) {
            pa = *(const float4*)(aptr + k0 + 8 + lc);
            pb = *(const float4*)(bptr + k0 + 8 + lc);
        }

#pragma unroll
        for (int k = 0; k < 8; k++) {
            float4 a0 = *(const float4*)&As[k][ty * 8];
            float4 a1 = *(const float4*)&As[k][ty * 8 + 4];
            float4 b0 = *(const float4*)&Bs[k][tx * 8];
            float4 b1 = *(const float4*)&Bs[k][tx * 8 + 4];
            unsigned long long bp0 = pk2(b0.x, b0.y), bp1 = pk2(b0.z, b0.w);
            unsigned long long bp2 = pk2(b1.x, b1.y), bp3 = pk2(b1.z, b1.w);
            float av[8] = {a0.x, a0.y, a0.z, a0.w, a1.x, a1.y, a1.z, a1.w};
#pragma unroll
            for (int i = 0; i < 8; i++) {
                unsigned long long ad = dup2(av[i]);
                fma2(accp[i][0], ad, bp0);
                fma2(accp[i][1], ad, bp1);
                fma2(accp[i][2], ad, bp2);
                fma2(accp[i][3], ad, bp3);
            }
        }
    }

#pragma unroll
    for (int i = 0; i < 8; i++) {
        int m = row0 + ty * 8 + i;
        float* op = g_table + (size_t)m * HID + col0 + tx * 8;
#pragma unroll
        for (int jp = 0; jp < 4; jp++) {
            float v0, v1;
            upk2(accp[i][jp], v0, v1);
            int n = col0 + tx * 8 + jp * 2;
            op[jp * 2]     = v0 + Wx_b[n]     + Wh_b[n];
            op[jp * 2 + 1] = v1 + Wx_b[n + 1] + Wh_b[n + 1];
        }
    }
}

// ---------------------------------------------------------------------------
// Cluster scan v3: 16 clusters x 8 CTAs, 512 threads.
// CTA = 64 j x 4 b. Weights in smem as j-paired u64 (conflict-free).
// h plain [k][4b] float4 -> (b0,b1)/(b2,b3) u64 pairs feed FFMA2 directly.
// One split cluster barrier per step (arrive after DSMEM stores, wait at top).
// ---------------------------------------------------------------------------
// smem bytes: swp 512*32*8 = 131072 | sh 2*512*16 = 16384 | srp 2048*8 = 16384
//             sidx 4*512*4 = 8192  -> total 172032
#define SWP_OFF_U64   0                      // u64 units
#define SH_OFF_F      (131072 / 4)           // float units  (32768)
#define SRP_OFF_U64   ((131072 + 16384) / 8) // u64 units    (18432)
#define SIDX_OFF_B    (131072 + 16384 + 16384)
#define SCAN_SMEM_BYTES (131072 + 16384 + 16384 + 8192)

// srp index: [ks(16)][bp(2)][jj(2)][jp(32)]
#define SRP_IDX(ks, bp, jj, jp) ((((ks) * 4) + ((bp) * 2) + (jj)) * 32 + (jp))

__global__ __launch_bounds__(512, 1) __cluster_dims__(8, 1, 1)
void scan_kernel(const int* __restrict__ q, const int* __restrict__ r,
                 const float* __restrict__ Wh_w,
                 const float* __restrict__ tau) {
    extern __shared__ char smem_raw[];
    unsigned long long* swp = (unsigned long long*)smem_raw;            // [512k][32jp]
    float*              shf = (float*)smem_raw + SH_OFF_F;              // [2][512][4b]
    unsigned long long* srp = (unsigned long long*)smem_raw + SRP_OFF_U64;
    int*                sidxm = (int*)(smem_raw + SIDX_OFF_B);          // [4b][512s]

    cg::cluster_group cluster = cg::this_cluster();
    const int rank = (int)cluster.block_rank();
    const int cid  = blockIdx.x >> 3;
    const int tid  = threadIdx.x;
    const int j0   = rank * 64;
    const int b0   = cid * 4;

    // ---- stage idx table ----
    for (int i = tid; i < 4 * SEQ; i += 512) {
        int b = i >> 9, s = i & 511;
        int m = (b0 + b) * SEQ + s;
        sidxm[i] = q[m] + NUM_C * r[m];
    }
    // ---- zero h buffer 0 ----
    for (int i = tid; i < 2048; i += 512) shf[i] = 0.0f;

    // ---- phase A mapping ----
    const int jp = tid & 31;            // j-pair -> j = 2jp, 2jp+1
    const int ks = tid >> 5;            // 0..15, 32 k each

    // ---- stage weights: swp[k][jp] = (Wh[j0+2jp][k], Wh[j0+2jp+1][k]) ----
    {
        const int kc = ks;              // 16 chunks x 32 k
        const float* r0 = Wh_w + (size_t)(j0 + 2 * jp)     * HID + kc * 32;
        const float* r1 = Wh_w + (size_t)(j0 + 2 * jp + 1) * HID + kc * 32;
#pragma unroll
        for (int t = 0; t < 8; t++) {
            float4 f0 = *(const float4*)(r0 + t * 4);
            float4 f1 = *(const float4*)(r1 + t * 4);
            int kb = kc * 32 + t * 4;
            swp[(kb + 0) * 32 + jp] = pk2(f0.x, f1.x);
            swp[(kb + 1) * 32 + jp] = pk2(f0.y, f1.y);
            swp[(kb + 2) * 32 + jp] = pk2(f0.z, f1.z);
            swp[(kb + 3) * 32 + jp] = pk2(f0.w, f1.w);
        }
    }

    // ---- phase B mapping (tid<128): jB = tid&63, bp = tid>>6 ----
    const int jB = tid & 63;
    const int bp = (tid >> 6) & 1;
    float itb = 1.0f;
    if (tid < 128) itb = 1.0f / tau[j0 + jB];

    // ---- phase C mapping: 448 threads, one float4 each ----
    const int pc_rem = tid & 63;
    int pc_rk = tid >> 6;               // 0..6 for tid<448
    if (pc_rk >= rank) pc_rk += 1;

    __syncthreads();
    cluster.sync();

    // pre-load xp for s = 0
    float xp0 = 0.f, xp1 = 0.f;
    if (tid < 128) {
        int row0i = sidxm[(2 * bp) * SEQ + 0];
        int row1i = sidxm[(2 * bp + 1) * SEQ + 0];
        xp0 = __ldcg(&g_table[(size_t)row0i * HID + j0 + jB]);
        xp1 = __ldcg(&g_table[(size_t)row1i * HID + j0 + jB]);
    }

    for (int s = 0; s < SEQ; s++) {
        if (s) CLUSTER_WAIT();          // peers' h slices for this step landed

        const float* shc = shf + (s & 1) * 2048;
        float*       shn = shf + ((s + 1) & 1) * 2048;

        float hold0 = 0.f, hold1 = 0.f;
        if (tid < 128) {
            float2 hf = *(const float2*)&shc[(j0 + jB) * 4 + 2 * bp];
            hold0 = hf.x; hold1 = hf.y;
        }

        // ---- phase A: 32 k per thread ----
        unsigned long long a00 = 0ull, a01 = 0ull, a10 = 0ull, a11 = 0ull;
        const unsigned long long* wp  = swp + (size_t)ks * 32 * 32 + jp;
        const ulonglong2*         hpp = (const ulonglong2*)shc + ks * 32;
#pragma unroll
        for (int kk = 0; kk < 32; kk++) {
            unsigned long long wpair = wp[kk * 32];       // (w_j0, w_j1)
            ulonglong2 hu = hpp[kk];                      // (hb0,hb1),(hb2,hb3)
            unsigned long long w00, w11;
            dupsplit(wpair, w00, w11);
            fma2(a00, w00, hu.x);   // j0 x (b0,b1)
            fma2(a01, w00, hu.y);   // j0 x (b2,b3)
            fma2(a10, w11, hu.x);   // j1 x (b0,b1)
            fma2(a11, w11, hu.y);   // j1 x (b2,b3)
        }
        srp[SRP_IDX(ks, 0, 0, jp)] = a00;
        srp[SRP_IDX(ks, 1, 0, jp)] = a01;
        srp[SRP_IDX(ks, 0, 1, jp)] = a10;
        srp[SRP_IDX(ks, 1, 1, jp)] = a11;
        __syncthreads();

        // ---- phase B (tid<128): reduce 16 slices, LTC update ----
        float hn0 = 0.f, hn1 = 0.f;
        if (tid < 128) {
            const int jj  = jB & 1;
            const int jph = jB >> 1;
            unsigned long long sa = srp[SRP_IDX(0, bp, jj, jph)];
            unsigned long long sb = srp[SRP_IDX(1, bp, jj, jph)];
#pragma unroll
            for (int k2 = 2; k2 < 16; k2 += 2) {
                add2(sa, srp[SRP_IDX(k2,     bp, jj, jph)]);
                add2(sb, srp[SRP_IDX(k2 + 1, bp, jj, jph)]);
            }
            add2(sa, sb);
            float f0, f1;
            upk2(sa, f0, f1);                 // f0: b=2bp, f1: b=2bp+1
            float th0 = tanhf(f0 + xp0);
            float th1 = tanhf(f1 + xp1);
            hn0 = hold0 + (th0 - hold0) * itb;
            hn1 = hold1 + (th1 - hold1) * itb;
            *(float2*)&shn[(j0 + jB) * 4 + 2 * bp] = make_float2(hn0, hn1);
        }
        __syncthreads();

        // ---- phase C: send own 1KB slice to 7 peers, then arrive ----
        if (s < SEQ - 1) {
            if (tid < 448) {
                float4* src = (float4*)(shn + j0 * 4) + pc_rem;
                float4  val = *src;
                float4* dst = cluster.map_shared_rank(src, pc_rk);
                *dst = val;
            }
            CLUSTER_ARRIVE();
        }

        // ---- deferred global store + next-step xp prefetch (overlaps wait) ----
        if (tid < 128) {
            g_hs[((size_t)(b0 + 2 * bp)     * SEQ + s) * HID + j0 + jB] = hn0;
            g_hs[((size_t)(b0 + 2 * bp + 1) * SEQ + s) * HID + j0 + jB] = hn1;
            if (s < SEQ - 1) {
                int row0i = sidxm[(2 * bp) * SEQ + s + 1];
                int row1i = sidxm[(2 * bp + 1) * SEQ + s + 1];
                xp0 = __ldcg(&g_table[(size_t)row0i * HID + j0 + jB]);
                xp1 = __ldcg(&g_table[(size_t)row1i * HID + j0 + jB]);
            }
        }
    }
}

// ---------------------------------------------------------------------------
// Output GEMM + sigmoid (f32x2 inner)
// ---------------------------------------------------------------------------
__global__ __launch_bounds__(256, 2)
void out_kernel(const float* __restrict__ Wo_w,
                const float* __restrict__ Wo_b,
                float* __restrict__ out) {
    __shared__ float As[8][128];
    __shared__ float Bs[8][128];

    const int tid  = threadIdx.x;
    const int row0 = blockIdx.y * 128;
    const int col0 = blockIdx.x * 128;

    const int lr = tid >> 1;
    const int lc = (tid & 1) * 4;
    const int tx = tid & 15;
    const int ty = tid >> 4;

    const float* aptr = g_hs + (size_t)(row0 + lr) * HID;
    const float* bptr = Wo_w + (size_t)(col0 + lr) * HID;

    unsigned long long accp[8][4];
#pragma unroll
    for (int i = 0; i < 8; i++)
#pragma unroll
        for (int j = 0; j < 4; j++) accp[i][j] = 0ull;

    float4 pa = *(const float4*)(aptr + lc);
    float4 pb = *(const float4*)(bptr + lc);

    for (int k0 = 0; k0 < HID; k0 += 8) {
        __syncthreads();
        As[lc + 0][lr] = pa.x; As[lc + 1][lr] = pa.y;
        As[lc + 2][lr] = pa.z; As[lc + 3][lr] = pa.w;
        Bs[lc + 0][lr] = pb.x; Bs[lc + 1][lr] = pb.y;
        Bs[lc + 2][lr] = pb.z; Bs[lc + 3][lr] = pb.w;
        __syncthreads();

        if (k0 + 8 < HID) {
            pa = *(const float4*)(aptr + k0 + 8 + lc);
            pb = *(const float4*)(bptr + k0 + 8 + lc);
        }

#pragma unroll
        for (int k = 0; k < 8; k++) {
            float4 a0 = *(const float4*)&As[k][ty * 8];
            float4 a1 = *(const float4*)&As[k][ty * 8 + 4];
            float4 b0 = *(const float4*)&Bs[k][tx * 8];
            float4 b1 = *(const float4*)&Bs[k][tx * 8 + 4];
            unsigned long long bp0 = pk2(b0.x, b0.y), bp1 = pk2(b0.z, b0.w);
            unsigned long long bp2 = pk2(b1.x, b1.y), bp3 = pk2(b1.z, b1.w);
            float av[8] = {a0.x, a0.y, a0.z, a0.w, a1.x, a1.y, a1.z, a1.w};
#pragma unroll
            for (int i = 0; i < 8; i++) {
                unsigned long long ad = dup2(av[i]);
                fma2(accp[i][0], ad, bp0);
                fma2(accp[i][1], ad, bp1);
                fma2(accp[i][2], ad, bp2);
                fma2(accp[i][3], ad, bp3);
            }
        }
    }

#pragma unroll
    for (int i = 0; i < 8; i++) {
        int m = row0 + ty * 8 + i;
        float* op = out + (size_t)m * NUM_C + col0 + tx * 8;
#pragma unroll
        for (int jp = 0; jp < 4; jp++) {
            float v0, v1;
            upk2(accp[i][jp], v0, v1);
            int n = col0 + tx * 8 + jp * 2;
            float l0 = v0 + Wo_b[n];
            float l1 = v1 + Wo_b[n + 1];
            op[jp * 2]     = 1.0f / (1.0f + expf(-l0));
            op[jp * 2 + 1] = 1.0f / (1.0f + expf(-l1));
        }
    }
}

// ---------------------------------------------------------------------------
extern "C" void kernel_launch(void* const* d_in, const int* in_sizes, int n_in,
                              void* d_out, int out_size) {
    const int*   q    = (const int*)  d_in[0];
    const int*   r    = (const int*)  d_in[1];
    const float* emb  = (const float*)d_in[2];
    const float* Wh_w = (const float*)d_in[3];
    const float* Wh_b = (const float*)d_in[4];
    const float* Wx_w = (const float*)d_in[5];
    const float* Wx_b = (const float*)d_in[6];
    const float* tau  = (const float*)d_in[7];
    const float* Wo_w = (const float*)d_in[8];
    const float* Wo_b = (const float*)d_in[9];
    float*       out  = (float*)d_out;

    cudaFuncSetAttribute(scan_kernel,
                         cudaFuncAttributeMaxDynamicSharedMemorySize,
                         SCAN_SMEM_BYTES);

    // 1) projection table: 2048 x 512 (biases folded)
    {
        dim3 grid(HID / 128, NROWS / 128);
        proj_kernel<<<grid, 256>>>(emb, Wx_w, Wx_b, Wh_b);
    }
    // 2) cluster scan: 128 CTAs = 16 clusters x 8 ranks, 512 threads
    scan_kernel<<<128, 512, SCAN_SMEM_BYTES>>>(q, r, Wh_w, tau);
    // 3) output GEMM + sigmoid
    {
        dim3 grid(NUM_C / 128, M_ROWS / 128);
        out_kernel<<<grid, 256>>>(Wo_w, Wo_b, out);
    }
}